// round 2
// baseline (speedup 1.0000x reference)
#include <cuda_runtime.h>

#define NB 4
#define NT 16384
#define NCH 32
#define NCOND 80
#define NLAY 40
#define TT 472
#define HALO 40
#define TTH 512
#define TILES_PER_B 35
#define NTHREADS 256

#define W_DIL 0
#define W_F   2048
#define W_G   3072
#define W_CF  4096
#define W_CG  6656
#define W_OUT 9216
#define W_TOTAL 10240

#define SMEM_FLOATS (32*TTH + 32*TTH + W_TOTAL + 32)
#define SMEM_BYTES  (SMEM_FLOATS * 4)

__device__ __forceinline__ float fast_sigmoid(float v) {
    v = fminf(fmaxf(v, -30.f), 30.f);
    return __fdividef(1.f, 1.f + __expf(-v));
}
__device__ __forceinline__ float fast_tanh(float v) {
    v = fminf(fmaxf(v, -15.f), 15.f);
    float e2 = __expf(2.f * v);
    return __fdividef(e2 - 1.f, e2 + 1.f);
}

__global__ void __launch_bounds__(NTHREADS, 1)
wavenet_kernel(const float* __restrict__ x, const float* __restrict__ h,
               const float* __restrict__ start_w, const float* __restrict__ dil_w,
               const float* __restrict__ f_w, const float* __restrict__ g_w,
               const float* __restrict__ cf_w, const float* __restrict__ cg_w,
               const float* __restrict__ out_w, const float* __restrict__ end1_w,
               const float* __restrict__ end2_w, float* __restrict__ out)
{
    extern __shared__ float smem[];
    float* res  = smem;             // [32][TTH]
    float* ybuf = smem + 32 * TTH;  // [32][TTH]
    float* wbuf = smem + 64 * TTH;  // [W_TOTAL]
    float* sw   = wbuf + W_TOTAL;   // [32]

    const int tid = threadIdx.x;
    const int b   = blockIdx.x / TILES_PER_B;
    const int tc  = blockIdx.x % TILES_PER_B;
    const int t0  = tc * TT;
    const int tgb = t0 - HALO;

    if (tid < 32) sw[tid] = start_w[tid];
    for (int idx = tid; idx < 32 * TTH; idx += NTHREADS) {
        int ch = idx >> 9, lt = idx & (TTH - 1);
        int tg = tgb + lt;
        float xv = (tg >= 0 && tg < NT) ? x[b * NT + tg] : 0.f;
        res[idx] = start_w[ch] * xv;
    }
    __syncthreads();

    const int ob  = tid >> 6;   // output-channel block (8 ch)
    const int tb  = tid & 63;   // time block (8 t)
    const int o0  = ob * 8;
    const int lt0 = tb * 8;

    for (int l = 0; l < NLAY; ++l) {
        { // stage weights
            const float* dl  = dil_w + l * 2048;
            const float* fl  = f_w   + l * 1024;
            const float* gl  = g_w   + l * 1024;
            const float* cfl = cf_w  + l * 2560;
            const float* cgl = cg_w  + l * 2560;
            const float* ol  = out_w + l * 1024;
            for (int j = tid; j < W_TOTAL; j += NTHREADS) {
                float v;
                if      (j < 2048) v = dl[j];
                else if (j < 3072) v = fl[j - 2048];
                else if (j < 4096) v = gl[j - 3072];
                else if (j < 6656) v = cfl[j - 4096];
                else if (j < 9216) v = cgl[j - 6656];
                else               v = ol[j - 9216];
                wbuf[j] = v;
            }
        }
        __syncthreads();

        // G1: y = W0@res[t-1] + W1@res[t]
        {
            float acc[8][8];
            #pragma unroll
            for (int a = 0; a < 8; ++a)
                #pragma unroll
                for (int c = 0; c < 8; ++c) acc[a][c] = 0.f;
            for (int i = 0; i < 32; ++i) {
                const float* rr = res + i * TTH + lt0;
                float xs[9];
                xs[0] = (lt0 > 0) ? rr[-1] : 0.f;
                float4 v0 = *(const float4*)rr;
                float4 v1 = *(const float4*)(rr + 4);
                xs[1]=v0.x; xs[2]=v0.y; xs[3]=v0.z; xs[4]=v0.w;
                xs[5]=v1.x; xs[6]=v1.y; xs[7]=v1.z; xs[8]=v1.w;
                const float* wp = wbuf + W_DIL + (o0 * 32 + i) * 2;
                #pragma unroll
                for (int oo = 0; oo < 8; ++oo) {
                    float w0 = wp[oo * 64], w1 = wp[oo * 64 + 1];
                    #pragma unroll
                    for (int t = 0; t < 8; ++t)
                        acc[oo][t] += w0 * xs[t] + w1 * xs[t + 1];
                }
            }
            #pragma unroll
            for (int oo = 0; oo < 8; ++oo) {
                float* yo = ybuf + (o0 + oo) * TTH + lt0;
                *(float4*)yo       = make_float4(acc[oo][0],acc[oo][1],acc[oo][2],acc[oo][3]);
                *(float4*)(yo + 4) = make_float4(acc[oo][4],acc[oo][5],acc[oo][6],acc[oo][7]);
            }
        }
        __syncthreads();

        // G2: z = tanh(F@y + CF@h) * sigmoid(G@y + CG@h); 512 tiles of 4ch x 8t
        float zst[2][4][8];
        #pragma unroll
        for (int p = 0; p < 2; ++p) {
            int tile = tid + p * NTHREADS;
            int cb = tile >> 6, tb2 = tile & 63;
            int c0 = cb * 4, lq = tb2 * 8;
            float pf[4][8], pg[4][8];
            #pragma unroll
            for (int a = 0; a < 4; ++a)
                #pragma unroll
                for (int c = 0; c < 8; ++c) { pf[a][c] = 0.f; pg[a][c] = 0.f; }
            for (int k = 0; k < 32; ++k) {
                const float* yr = ybuf + k * TTH + lq;
                float4 v0 = *(const float4*)yr;
                float4 v1 = *(const float4*)(yr + 4);
                float yv[8] = {v0.x,v0.y,v0.z,v0.w,v1.x,v1.y,v1.z,v1.w};
                const float* wfp = wbuf + W_F + c0 * 32 + k;
                const float* wgp = wbuf + W_G + c0 * 32 + k;
                #pragma unroll
                for (int cc = 0; cc < 4; ++cc) {
                    float wf = wfp[cc * 32], wg = wgp[cc * 32];
                    #pragma unroll
                    for (int t = 0; t < 8; ++t) {
                        pf[cc][t] += wf * yv[t];
                        pg[cc][t] += wg * yv[t];
                    }
                }
            }
            int tg0 = tgb + lq;
            if (tg0 >= 0 && tg0 + 8 <= NT) {
                for (int k = 0; k < NCOND; ++k) {
                    const float* hr = h + ((size_t)(b * NCOND + k)) * NT + tg0;
                    float4 v0 = *(const float4*)hr;
                    float4 v1 = *(const float4*)(hr + 4);
                    float hv[8] = {v0.x,v0.y,v0.z,v0.w,v1.x,v1.y,v1.z,v1.w};
                    const float* wcfp = wbuf + W_CF + c0 * NCOND + k;
                    const float* wcgp = wbuf + W_CG + c0 * NCOND + k;
                    #pragma unroll
                    for (int cc = 0; cc < 4; ++cc) {
                        float wf = wcfp[cc * NCOND], wg = wcgp[cc * NCOND];
                        #pragma unroll
                        for (int t = 0; t < 8; ++t) {
                            pf[cc][t] += wf * hv[t];
                            pg[cc][t] += wg * hv[t];
                        }
                    }
                }
            }
            #pragma unroll
            for (int cc = 0; cc < 4; ++cc)
                #pragma unroll
                for (int t = 0; t < 8; ++t)
                    zst[p][cc][t] = fast_tanh(pf[cc][t]) * fast_sigmoid(pg[cc][t]);
        }
        __syncthreads();  // all reads of Y done
        #pragma unroll
        for (int p = 0; p < 2; ++p) {
            int tile = tid + p * NTHREADS;
            int cb = tile >> 6, tb2 = tile & 63;
            int c0 = cb * 4, lq = tb2 * 8;
            #pragma unroll
            for (int cc = 0; cc < 4; ++cc) {
                float* zo = ybuf + (c0 + cc) * TTH + lq;
                *(float4*)zo       = make_float4(zst[p][cc][0],zst[p][cc][1],zst[p][cc][2],zst[p][cc][3]);
                *(float4*)(zo + 4) = make_float4(zst[p][cc][4],zst[p][cc][5],zst[p][cc][6],zst[p][cc][7]);
            }
        }
        __syncthreads();

        // G3: res += Ow @ z  (freeze global t<0 pad region)
        {
            float acc[8][8];
            #pragma unroll
            for (int a = 0; a < 8; ++a)
                #pragma unroll
                for (int c = 0; c < 8; ++c) acc[a][c] = 0.f;
            for (int k = 0; k < 32; ++k) {
                const float* zr = ybuf + k * TTH + lt0;
                float4 v0 = *(const float4*)zr;
                float4 v1 = *(const float4*)(zr + 4);
                float zv[8] = {v0.x,v0.y,v0.z,v0.w,v1.x,v1.y,v1.z,v1.w};
                const float* wp = wbuf + W_OUT + o0 * 32 + k;
                #pragma unroll
                for (int oo = 0; oo < 8; ++oo) {
                    float w = wp[oo * 32];
                    #pragma unroll
                    for (int t = 0; t < 8; ++t)
                        acc[oo][t] += w * zv[t];
                }
            }
            if (tgb + lt0 >= 0) {
                #pragma unroll
                for (int oo = 0; oo < 8; ++oo)
                    #pragma unroll
                    for (int t = 0; t < 8; ++t)
                        res[(o0 + oo) * TTH + lt0 + t] += acc[oo][t];
            }
        }
        __syncthreads();
    }

    // relu(skip) = relu(res - start_w*x) -> ybuf
    for (int idx = tid; idx < 32 * TTH; idx += NTHREADS) {
        int ch = idx >> 9, lt = idx & (TTH - 1);
        int tg = tgb + lt;
        float xv = (tg >= 0 && tg < NT) ? x[b * NT + tg] : 0.f;
        ybuf[idx] = fmaxf(res[idx] - sw[ch] * xv, 0.f);
    }
    __syncthreads();

    // end head, 64-timestep chunks; ebuf[256][64] reuses res
    float* ebuf = res;
    const int sb  = tid >> 3;  // 0..31
    const int tb8 = tid & 7;   // 0..7
    for (int chunk = 0; chunk < 8; ++chunk) {
        int ltc = HALO + chunk * 64 + tb8 * 8;
        bool active = (ltc < TTH);
        if (active) { // E1: e = relu(end1 @ skip)
            int s0 = sb * 8;
            float acc[8][8];
            #pragma unroll
            for (int a = 0; a < 8; ++a)
                #pragma unroll
                for (int c = 0; c < 8; ++c) acc[a][c] = 0.f;
            for (int k = 0; k < 32; ++k) {
                const float* yr = ybuf + k * TTH + ltc;
                float4 v0 = *(const float4*)yr;
                float4 v1 = *(const float4*)(yr + 4);
                float yv[8] = {v0.x,v0.y,v0.z,v0.w,v1.x,v1.y,v1.z,v1.w};
                const float* wp = end1_w + s0 * 32 + k;
                #pragma unroll
                for (int ss = 0; ss < 8; ++ss) {
                    float w = __ldg(wp + ss * 32);
                    #pragma unroll
                    for (int t = 0; t < 8; ++t)
                        acc[ss][t] += w * yv[t];
                }
            }
            #pragma unroll
            for (int ss = 0; ss < 8; ++ss) {
                float* eo = ebuf + (s0 + ss) * 64 + tb8 * 8;
                *(float4*)eo       = make_float4(fmaxf(acc[ss][0],0.f),fmaxf(acc[ss][1],0.f),
                                                 fmaxf(acc[ss][2],0.f),fmaxf(acc[ss][3],0.f));
                *(float4*)(eo + 4) = make_float4(fmaxf(acc[ss][4],0.f),fmaxf(acc[ss][5],0.f),
                                                 fmaxf(acc[ss][6],0.f),fmaxf(acc[ss][7],0.f));
            }
        }
        __syncthreads();
        if (active) { // E2: logit = end2 @ e
            int c0 = sb * 8;
            float acc[8][8];
            #pragma unroll
            for (int a = 0; a < 8; ++a)
                #pragma unroll
                for (int c = 0; c < 8; ++c) acc[a][c] = 0.f;
            for (int k = 0; k < 256; ++k) {
                const float* er = ebuf + k * 64 + tb8 * 8;
                float4 v0 = *(const float4*)er;
                float4 v1 = *(const float4*)(er + 4);
                float ev[8] = {v0.x,v0.y,v0.z,v0.w,v1.x,v1.y,v1.z,v1.w};
                const float* wp = end2_w + c0 * 256 + k;
                #pragma unroll
                for (int cc = 0; cc < 8; ++cc) {
                    float w = __ldg(wp + cc * 256);
                    #pragma unroll
                    for (int t = 0; t < 8; ++t)
                        acc[cc][t] += w * ev[t];
                }
            }
            int tgc = tgb + ltc;
            #pragma unroll
            for (int cc = 0; cc < 8; ++cc)
                #pragma unroll
                for (int t = 0; t < 8; ++t) {
                    int tg = tgc + t;
                    if (tg < NT)
                        out[((size_t)(b * 256 + c0 + cc)) * NT + tg] = acc[cc][t];
                }
        }
        __syncthreads();
    }
}

extern "C" void kernel_launch(void* const* d_in, const int* in_sizes, int n_in,
                              void* d_out, int out_size) {
    const float* x       = (const float*)d_in[0];
    const float* h       = (const float*)d_in[1];
    const float* start_w = (const float*)d_in[2];
    const float* dil_w   = (const float*)d_in[3];
    const float* f_w     = (const float*)d_in[4];
    const float* g_w     = (const float*)d_in[5];
    const float* cf_w    = (const float*)d_in[6];
    const float* cg_w    = (const float*)d_in[7];
    const float* out_w   = (const float*)d_in[8];
    const float* end1_w  = (const float*)d_in[9];
    const float* end2_w  = (const float*)d_in[10];
    float* out = (float*)d_out;

    cudaFuncSetAttribute(wavenet_kernel,
                         cudaFuncAttributeMaxDynamicSharedMemorySize, SMEM_BYTES);
    wavenet_kernel<<<NB * TILES_PER_B, NTHREADS, SMEM_BYTES>>>(
        x, h, start_w, dil_w, f_w, g_w, cf_w, cg_w, out_w, end1_w, end2_w, out);
}

// round 4
// speedup vs baseline: 2.0758x; 2.0758x over previous
#include <cuda_runtime.h>

#define NB 4
#define NT 16384
#define NCOND 80
#define NLAY 40
#define TT 472
#define HALO 40
#define TTH 512
#define TILES_PER_B 35
#define NTHREADS 512

// duplicated-weight smem offsets (floats, within wdup)
#define D2  0        // dil  32*32*2 dup -> 4096
#define F2  4096     // f    1024 dup -> 2048
#define G2o 6144     // g    -> 2048
#define CF2 8192     // cf   2560 dup -> 5120
#define CG2 13312    // cg   -> 5120
#define O2  18432    // out  -> 2048
#define WDUP_TOTAL 20480

#define SMEM_FLOATS (32*TTH + 32*TTH + WDUP_TOTAL + 32)
#define SMEM_BYTES  (SMEM_FLOATS * 4)

typedef unsigned long long u64;

__device__ __forceinline__ u64 pk(float lo, float hi) {
    u64 r; asm("mov.b64 %0,{%1,%2};" : "=l"(r) : "f"(lo), "f"(hi)); return r;
}
__device__ __forceinline__ void upk(u64 v, float& a, float& b) {
    asm("mov.b64 {%0,%1},%2;" : "=f"(a), "=f"(b) : "l"(v));
}
__device__ __forceinline__ u64 fma2(u64 a, u64 b, u64 c) {
    u64 d; asm("fma.rn.f32x2 %0,%1,%2,%3;" : "=l"(d) : "l"(a), "l"(b), "l"(c)); return d;
}
__device__ __forceinline__ u64 add2(u64 a, u64 b) {
    u64 d; asm("add.rn.f32x2 %0,%1,%2;" : "=l"(d) : "l"(a), "l"(b)); return d;
}

__device__ __forceinline__ float fast_sigmoid(float v) {
    v = fminf(fmaxf(v, -30.f), 30.f);
    return __fdividef(1.f, 1.f + __expf(-v));
}
__device__ __forceinline__ float fast_tanh(float v) {
    v = fminf(fmaxf(v, -15.f), 15.f);
    float e2 = __expf(2.f * v);
    return __fdividef(e2 - 1.f, e2 + 1.f);
}

__global__ void __launch_bounds__(NTHREADS, 1)
wavenet_kernel(const float* __restrict__ x, const float* __restrict__ h,
               const float* __restrict__ start_w, const float* __restrict__ dil_w,
               const float* __restrict__ f_w, const float* __restrict__ g_w,
               const float* __restrict__ cf_w, const float* __restrict__ cg_w,
               const float* __restrict__ out_w, const float* __restrict__ end1_w,
               const float* __restrict__ end2_w, float* __restrict__ out)
{
    extern __shared__ float smem[];
    float* res  = smem;               // [32][TTH]
    float* ybuf = smem + 32 * TTH;    // [32][TTH]
    float* wd   = smem + 64 * TTH;    // [WDUP_TOTAL] duplicated weights
    float* sw   = wd + WDUP_TOTAL;    // [32]

    const int tid = threadIdx.x;
    const int b   = blockIdx.x / TILES_PER_B;
    const int tc  = blockIdx.x % TILES_PER_B;
    const int tgb = tc * TT - HALO;

    if (tid < 32) sw[tid] = start_w[tid];
    for (int idx = tid; idx < 32 * TTH; idx += NTHREADS) {
        int ch = idx >> 9, lt = idx & (TTH - 1);
        int tg = tgb + lt;
        float xv = (tg >= 0 && tg < NT) ? x[b * NT + tg] : 0.f;
        res[idx] = start_w[ch] * xv;
    }
    __syncthreads();

    const int cb  = tid >> 6;     // 0..7  : channel block of 4
    const int tb  = tid & 63;     // 0..63 : time block of 8
    const int c0  = cb * 4;
    const int lt0 = tb * 8;

    for (int l = 0; l < NLAY; ++l) {
        { // stage this layer's weights, duplicated (w,w)
            const float* dl  = dil_w + l * 2048;
            const float* fl  = f_w   + l * 1024;
            const float* gl  = g_w   + l * 1024;
            const float* cfl = cf_w  + l * 2560;
            const float* cgl = cg_w  + l * 2560;
            const float* ol  = out_w + l * 1024;
            for (int j = tid; j < 10240; j += NTHREADS) {
                float v; int d;
                if      (j < 2048) { v = dl[j];         d = D2  + 2*j; }
                else if (j < 3072) { v = fl[j - 2048];  d = F2  + 2*(j-2048); }
                else if (j < 4096) { v = gl[j - 3072];  d = G2o + 2*(j-3072); }
                else if (j < 6656) { v = cfl[j - 4096]; d = CF2 + 2*(j-4096); }
                else if (j < 9216) { v = cgl[j - 6656]; d = CG2 + 2*(j-6656); }
                else               { v = ol[j - 9216];  d = O2  + 2*(j-9216); }
                *(float2*)(wd + d) = make_float2(v, v);
            }
        }
        __syncthreads();

        // ---- G1: y[c,t] = W0[c,i]*res[i,t-1] + W1[c,i]*res[i,t] ----
        {
            u64 acc[4][4];
            #pragma unroll
            for (int a = 0; a < 4; ++a)
                #pragma unroll
                for (int p = 0; p < 4; ++p) acc[a][p] = 0ULL;

            for (int i = 0; i < 32; ++i) {
                const float* rr = res + i * TTH + lt0;
                ulonglong2 cA = *(const ulonglong2*)rr;
                ulonglong2 cB = *(const ulonglong2*)(rr + 4);
                u64 c_[4] = {cA.x, cA.y, cB.x, cB.y};     // (r0,r1)(r2,r3)(r4,r5)(r6,r7)
                float r0,r1,r2,r3,r4,r5,r6,r7;
                upk(c_[0],r0,r1); upk(c_[1],r2,r3); upk(c_[2],r4,r5); upk(c_[3],r6,r7);
                float rm1 = (lt0 > 0) ? rr[-1] : 0.f;
                u64 d_[4] = { pk(rm1,r0), pk(r1,r2), pk(r3,r4), pk(r5,r6) }; // (r[t-1],r[t]) pairs
                const float* wp = wd + D2 + i * 4;        // + (c)*128
                #pragma unroll
                for (int oo = 0; oo < 4; ++oo) {
                    u64 w0p = *(const u64*)(wp + (c0 + oo) * 128);
                    u64 w1p = *(const u64*)(wp + (c0 + oo) * 128 + 2);
                    #pragma unroll
                    for (int p = 0; p < 4; ++p) {
                        acc[oo][p] = fma2(d_[p], w0p, acc[oo][p]);
                        acc[oo][p] = fma2(c_[p], w1p, acc[oo][p]);
                    }
                }
            }
            #pragma unroll
            for (int oo = 0; oo < 4; ++oo) {
                float* yo = ybuf + (c0 + oo) * TTH + lt0;
                *(ulonglong2*)yo       = make_ulonglong2(acc[oo][0], acc[oo][1]);
                *(ulonglong2*)(yo + 4) = make_ulonglong2(acc[oo][2], acc[oo][3]);
            }
        }
        __syncthreads();

        // ---- G2: z = tanh(F@y + CF@h) * sigmoid(G@y + CG@h) ----
        u64 zp[4][4];
        {
            u64 pf[4][4], pg[4][4];
            #pragma unroll
            for (int a = 0; a < 4; ++a)
                #pragma unroll
                for (int p = 0; p < 4; ++p) { pf[a][p] = 0ULL; pg[a][p] = 0ULL; }

            for (int k = 0; k < 32; ++k) {
                const float* yr = ybuf + k * TTH + lt0;
                ulonglong2 vA = *(const ulonglong2*)yr;
                ulonglong2 vB = *(const ulonglong2*)(yr + 4);
                u64 yv[4] = {vA.x, vA.y, vB.x, vB.y};
                #pragma unroll
                for (int cc = 0; cc < 4; ++cc) {
                    u64 wf = *(const u64*)(wd + F2  + (c0 + cc) * 64 + 2 * k);
                    u64 wg = *(const u64*)(wd + G2o + (c0 + cc) * 64 + 2 * k);
                    #pragma unroll
                    for (int p = 0; p < 4; ++p) {
                        pf[cc][p] = fma2(yv[p], wf, pf[cc][p]);
                        pg[cc][p] = fma2(yv[p], wg, pg[cc][p]);
                    }
                }
            }
            int tg0 = tgb + lt0;
            if (tg0 >= 0 && tg0 + 8 <= NT) {
                const float* hb = h + ((size_t)(b * NCOND)) * NT + tg0;
                for (int k = 0; k < NCOND; ++k) {
                    const float* hr = hb + (size_t)k * NT;
                    ulonglong2 vA = *(const ulonglong2*)hr;
                    ulonglong2 vB = *(const ulonglong2*)(hr + 4);
                    u64 hv[4] = {vA.x, vA.y, vB.x, vB.y};
                    #pragma unroll
                    for (int cc = 0; cc < 4; ++cc) {
                        u64 wf = *(const u64*)(wd + CF2 + (c0 + cc) * 160 + 2 * k);
                        u64 wg = *(const u64*)(wd + CG2 + (c0 + cc) * 160 + 2 * k);
                        #pragma unroll
                        for (int p = 0; p < 4; ++p) {
                            pf[cc][p] = fma2(hv[p], wf, pf[cc][p]);
                            pg[cc][p] = fma2(hv[p], wg, pg[cc][p]);
                        }
                    }
                }
            }
            #pragma unroll
            for (int cc = 0; cc < 4; ++cc)
                #pragma unroll
                for (int p = 0; p < 4; ++p) {
                    float f0, f1, g0, g1;
                    upk(pf[cc][p], f0, f1); upk(pg[cc][p], g0, g1);
                    zp[cc][p] = pk(fast_tanh(f0) * fast_sigmoid(g0),
                                   fast_tanh(f1) * fast_sigmoid(g1));
                }
        }
        __syncthreads();   // all reads of y done
        #pragma unroll
        for (int cc = 0; cc < 4; ++cc) {
            float* zo = ybuf + (c0 + cc) * TTH + lt0;
            *(ulonglong2*)zo       = make_ulonglong2(zp[cc][0], zp[cc][1]);
            *(ulonglong2*)(zo + 4) = make_ulonglong2(zp[cc][2], zp[cc][3]);
        }
        __syncthreads();   // z complete

        // ---- G3: res += Ow @ z ----
        {
            u64 acc[4][4];
            #pragma unroll
            for (int a = 0; a < 4; ++a)
                #pragma unroll
                for (int p = 0; p < 4; ++p) acc[a][p] = 0ULL;

            for (int k = 0; k < 32; ++k) {
                const float* zr = ybuf + k * TTH + lt0;
                ulonglong2 vA = *(const ulonglong2*)zr;
                ulonglong2 vB = *(const ulonglong2*)(zr + 4);
                u64 zv[4] = {vA.x, vA.y, vB.x, vB.y};
                #pragma unroll
                for (int oo = 0; oo < 4; ++oo) {
                    u64 w = *(const u64*)(wd + O2 + (c0 + oo) * 64 + 2 * k);
                    #pragma unroll
                    for (int p = 0; p < 4; ++p)
                        acc[oo][p] = fma2(zv[p], w, acc[oo][p]);
                }
            }
            if (tgb + lt0 >= 0) {
                #pragma unroll
                for (int oo = 0; oo < 4; ++oo) {
                    float* rp = res + (c0 + oo) * TTH + lt0;
                    ulonglong2 rA = *(const ulonglong2*)rp;
                    ulonglong2 rB = *(const ulonglong2*)(rp + 4);
                    *(ulonglong2*)rp       = make_ulonglong2(add2(rA.x, acc[oo][0]),
                                                             add2(rA.y, acc[oo][1]));
                    *(ulonglong2*)(rp + 4) = make_ulonglong2(add2(rB.x, acc[oo][2]),
                                                             add2(rB.y, acc[oo][3]));
                }
            }
        }
        __syncthreads();
    }

    // ---- relu(skip) = relu(res - start_w*x) -> ybuf; stage end1 dup into wd ----
    for (int idx = tid; idx < 32 * TTH; idx += NTHREADS) {
        int ch = idx >> 9, lt = idx & (TTH - 1);
        int tg = tgb + lt;
        float xv = (tg >= 0 && tg < NT) ? x[b * NT + tg] : 0.f;
        ybuf[idx] = fmaxf(res[idx] - sw[ch] * xv, 0.f);
    }
    for (int j = tid; j < 8192; j += NTHREADS) {   // end1_w [256][32] duplicated
        float v = end1_w[j];
        *(float2*)(wd + 2 * j) = make_float2(v, v);
    }
    __syncthreads();

    // ---- end head: chunks of 64 timesteps; ebuf[256][64] reuses res ----
    float* ebuf = res;
    const int cb2 = tid >> 3;   // 0..63 : block of 4 channels (of 256)
    const int tb8 = tid & 7;    // 0..7  : block of 8 timesteps
    const int s0  = cb2 * 4;
    for (int chunk = 0; chunk < 8; ++chunk) {
        int ltc = HALO + chunk * 64 + tb8 * 8;
        bool active = (ltc < TTH);
        if (active) {  // E1: e = relu(end1 @ skip)
            u64 acc[4][4];
            #pragma unroll
            for (int a = 0; a < 4; ++a)
                #pragma unroll
                for (int p = 0; p < 4; ++p) acc[a][p] = 0ULL;
            for (int k = 0; k < 32; ++k) {
                const float* yr = ybuf + k * TTH + ltc;
                ulonglong2 vA = *(const ulonglong2*)yr;
                ulonglong2 vB = *(const ulonglong2*)(yr + 4);
                u64 yv[4] = {vA.x, vA.y, vB.x, vB.y};
                #pragma unroll
                for (int ss = 0; ss < 4; ++ss) {
                    u64 w = *(const u64*)(wd + 2 * ((s0 + ss) * 32 + k));
                    #pragma unroll
                    for (int p = 0; p < 4; ++p)
                        acc[ss][p] = fma2(yv[p], w, acc[ss][p]);
                }
            }
            #pragma unroll
            for (int ss = 0; ss < 4; ++ss) {
                float* eo = ebuf + (s0 + ss) * 64 + tb8 * 8;
                #pragma unroll
                for (int p = 0; p < 4; ++p) {
                    float a0, a1; upk(acc[ss][p], a0, a1);
                    *(float2*)(eo + 2 * p) = make_float2(fmaxf(a0, 0.f), fmaxf(a1, 0.f));
                }
            }
        }
        __syncthreads();
        if (active) {  // E2: logit = end2 @ e
            u64 acc[4][4];
            #pragma unroll
            for (int a = 0; a < 4; ++a)
                #pragma unroll
                for (int p = 0; p < 4; ++p) acc[a][p] = 0ULL;
            for (int k = 0; k < 256; ++k) {
                const float* er = ebuf + k * 64 + tb8 * 8;
                ulonglong2 vA = *(const ulonglong2*)er;
                ulonglong2 vB = *(const ulonglong2*)(er + 4);
                u64 ev[4] = {vA.x, vA.y, vB.x, vB.y};
                #pragma unroll
                for (int cc = 0; cc < 4; ++cc) {
                    float w = __ldg(end2_w + (s0 + cc) * 256 + k);
                    u64 wp = pk(w, w);
                    #pragma unroll
                    for (int p = 0; p < 4; ++p)
                        acc[cc][p] = fma2(ev[p], wp, acc[cc][p]);
                }
            }
            int tgc = tgb + ltc;
            #pragma unroll
            for (int cc = 0; cc < 4; ++cc) {
                float* op = out + ((size_t)(b * 256 + s0 + cc)) * NT + tgc;
                if (tgc + 8 <= NT) {
                    #pragma unroll
                    for (int p = 0; p < 4; ++p)
                        *(u64*)(op + 2 * p) = acc[cc][p];
                } else {
                    #pragma unroll
                    for (int p = 0; p < 4; ++p) {
                        float a0, a1; upk(acc[cc][p], a0, a1);
                        if (tgc + 2 * p     < NT) op[2 * p]     = a0;
                        if (tgc + 2 * p + 1 < NT) op[2 * p + 1] = a1;
                    }
                }
            }
        }
        __syncthreads();
    }
}

extern "C" void kernel_launch(void* const* d_in, const int* in_sizes, int n_in,
                              void* d_out, int out_size) {
    const float* x       = (const float*)d_in[0];
    const float* h       = (const float*)d_in[1];
    const float* start_w = (const float*)d_in[2];
    const float* dil_w   = (const float*)d_in[3];
    const float* f_w     = (const float*)d_in[4];
    const float* g_w     = (const float*)d_in[5];
    const float* cf_w    = (const float*)d_in[6];
    const float* cg_w    = (const float*)d_in[7];
    const float* out_w   = (const float*)d_in[8];
    const float* end1_w  = (const float*)d_in[9];
    const float* end2_w  = (const float*)d_in[10];
    float* out = (float*)d_out;

    cudaFuncSetAttribute(wavenet_kernel,
                         cudaFuncAttributeMaxDynamicSharedMemorySize, SMEM_BYTES);
    wavenet_kernel<<<NB * TILES_PER_B, NTHREADS, SMEM_BYTES>>>(
        x, h, start_w, dil_w, f_w, g_w, cf_w, cg_w, out_w, end1_w, end2_w, out);
}

// round 5
// speedup vs baseline: 2.0910x; 1.0073x over previous
#include <cuda_runtime.h>

#define NB 4
#define NT 16384
#define NCOND 80
#define NLAY 40
#define TT 472
#define HALO 40
#define TTH 512
#define TILES_PER_B 35
#define NTHREADS 512

// transposed, pair-duplicated weight offsets (floats) within wd
#define D0T 0       // dil k=0 taps: [i][c] dup -> 2048
#define D1T 2048    // dil k=1 taps
#define F2T 4096    // f  [k][c] dup -> 2048
#define G2T 6144
#define CF2T 8192   // cf [k=0..79][c] dup -> 5120
#define CG2T 13312
#define O2T 18432
#define WTOT 20480

#define SMEM_FLOATS (32*TTH + 32*TTH + WTOT + 32)
#define SMEM_BYTES  (SMEM_FLOATS * 4)

typedef unsigned long long u64;

__device__ __forceinline__ u64 pk(float lo, float hi) {
    u64 r; asm("mov.b64 %0,{%1,%2};" : "=l"(r) : "f"(lo), "f"(hi)); return r;
}
__device__ __forceinline__ void upk(u64 v, float& a, float& b) {
    asm("mov.b64 {%0,%1},%2;" : "=f"(a), "=f"(b) : "l"(v));
}
__device__ __forceinline__ u64 fma2(u64 a, u64 b, u64 c) {
    u64 d; asm("fma.rn.f32x2 %0,%1,%2,%3;" : "=l"(d) : "l"(a), "l"(b), "l"(c)); return d;
}
__device__ __forceinline__ u64 add2(u64 a, u64 b) {
    u64 d; asm("add.rn.f32x2 %0,%1,%2;" : "=l"(d) : "l"(a), "l"(b)); return d;
}
__device__ __forceinline__ float fast_sigmoid(float v) {
    v = fminf(fmaxf(v, -30.f), 30.f);
    return __fdividef(1.f, 1.f + __expf(-v));
}
__device__ __forceinline__ float fast_tanh(float v) {
    v = fminf(fmaxf(v, -15.f), 15.f);
    float e2 = __expf(2.f * v);
    return __fdividef(e2 - 1.f, e2 + 1.f);
}

__global__ void __launch_bounds__(NTHREADS, 1)
wavenet_kernel(const float* __restrict__ x, const float* __restrict__ h,
               const float* __restrict__ start_w, const float* __restrict__ dil_w,
               const float* __restrict__ f_w, const float* __restrict__ g_w,
               const float* __restrict__ cf_w, const float* __restrict__ cg_w,
               const float* __restrict__ out_w, const float* __restrict__ end1_w,
               const float* __restrict__ end2_w, float* __restrict__ out)
{
    extern __shared__ float smem[];
    float* res  = smem;               // [32][TTH]
    float* ybuf = smem + 32 * TTH;    // [32][TTH]
    float* wd   = smem + 64 * TTH;    // [WTOT]
    float* sw   = wd + WTOT;          // [32]

    const int tid = threadIdx.x;
    const int b   = blockIdx.x / TILES_PER_B;
    const int tc  = blockIdx.x % TILES_PER_B;
    const int tgb = tc * TT - HALO;

    if (tid < 32) sw[tid] = start_w[tid];
    for (int idx = tid; idx < 32 * TTH; idx += NTHREADS) {
        int ch = idx >> 9, lt = idx & (TTH - 1);
        int tg = tgb + lt;
        float xv = (tg >= 0 && tg < NT) ? x[b * NT + tg] : 0.f;
        res[idx] = start_w[ch] * xv;
    }
    __syncthreads();

    const int cb  = tid >> 6;     // 0..7  channel block of 4
    const int tb  = tid & 63;     // 0..63 time block of 8
    const int c0  = cb * 4;
    const int lt0 = tb * 8;
    const int tg0 = tgb + lt0;
    const bool hval = (tg0 >= 0 && tg0 + 8 <= NT);
    const float* hb = h + ((size_t)(b * NCOND)) * NT + tg0;

    for (int l = 0; l < NLAY; ++l) {
        // ---- stage weights: transposed [k][c], duplicated (w,w) ----
        {
            const float* dl = dil_w + l * 2048;
            for (int j = tid; j < 1024; j += NTHREADS) {
                int c = j >> 5, i = j & 31;
                float2 w = *(const float2*)(dl + 2 * j);
                int d = (i * 32 + c) * 2;
                *(float2*)(wd + D0T + d) = make_float2(w.x, w.x);
                *(float2*)(wd + D1T + d) = make_float2(w.y, w.y);
            }
            const float* fl = f_w + l * 1024;
            const float* gl = g_w + l * 1024;
            for (int j = tid; j < 1024; j += NTHREADS) {
                int c = j >> 5, k = j & 31;
                int d = (k * 32 + c) * 2;
                float vf = fl[j], vg = gl[j];
                *(float2*)(wd + F2T + d) = make_float2(vf, vf);
                *(float2*)(wd + G2T + d) = make_float2(vg, vg);
            }
            const float* cfl = cf_w + l * 2560;
            const float* cgl = cg_w + l * 2560;
            for (int j = tid; j < 2560; j += NTHREADS) {
                int c = j / 80, k = j - c * 80;
                int d = (k * 32 + c) * 2;
                float vf = cfl[j], vg = cgl[j];
                *(float2*)(wd + CF2T + d) = make_float2(vf, vf);
                *(float2*)(wd + CG2T + d) = make_float2(vg, vg);
            }
            const float* ol = out_w + l * 1024;
            for (int j = tid; j < 1024; j += NTHREADS) {
                int c = j >> 5, k = j & 31;
                float v = ol[j];
                *(float2*)(wd + O2T + (k * 32 + c) * 2) = make_float2(v, v);
            }
        }
        __syncthreads();

        // ---- G1: y[c,t] = W0[c,i]*res[i,t-1] + W1[c,i]*res[i,t] ----
        {
            u64 acc[4][4];
            #pragma unroll
            for (int a = 0; a < 4; ++a)
                #pragma unroll
                for (int p = 0; p < 4; ++p) acc[a][p] = 0ULL;

            #pragma unroll 2
            for (int i = 0; i < 32; ++i) {
                const float* rr = res + i * TTH + lt0;
                ulonglong2 cA = *(const ulonglong2*)rr;
                ulonglong2 cB = *(const ulonglong2*)(rr + 4);
                const float* w0p = wd + D0T + (i * 32 + c0) * 2;
                const float* w1p = wd + D1T + (i * 32 + c0) * 2;
                ulonglong2 w0A = *(const ulonglong2*)w0p;
                ulonglong2 w0B = *(const ulonglong2*)(w0p + 4);
                ulonglong2 w1A = *(const ulonglong2*)w1p;
                ulonglong2 w1B = *(const ulonglong2*)(w1p + 4);
                u64 c_[4] = {cA.x, cA.y, cB.x, cB.y};
                float r0,r1,r2,r3,r4,r5,r6,r7;
                upk(c_[0],r0,r1); upk(c_[1],r2,r3); upk(c_[2],r4,r5); upk(c_[3],r6,r7);
                float rm1 = (lt0 > 0) ? rr[-1] : 0.f;
                u64 d_[4] = { pk(rm1,r0), pk(r1,r2), pk(r3,r4), pk(r5,r6) };
                u64 w0_[4] = {w0A.x, w0A.y, w0B.x, w0B.y};
                u64 w1_[4] = {w1A.x, w1A.y, w1B.x, w1B.y};
                #pragma unroll
                for (int cc = 0; cc < 4; ++cc)
                    #pragma unroll
                    for (int p = 0; p < 4; ++p) {
                        acc[cc][p] = fma2(d_[p], w0_[cc], acc[cc][p]);
                        acc[cc][p] = fma2(c_[p], w1_[cc], acc[cc][p]);
                    }
            }
            #pragma unroll
            for (int oo = 0; oo < 4; ++oo) {
                float* yo = ybuf + (c0 + oo) * TTH + lt0;
                *(ulonglong2*)yo       = make_ulonglong2(acc[oo][0], acc[oo][1]);
                *(ulonglong2*)(yo + 4) = make_ulonglong2(acc[oo][2], acc[oo][3]);
            }
        }
        __syncthreads();

        // ---- G2: z = tanh(F@y + CF@h) * sigmoid(G@y + CG@h) ----
        u64 zp[4][4];
        {
            u64 pf[4][4], pg[4][4];
            #pragma unroll
            for (int a = 0; a < 4; ++a)
                #pragma unroll
                for (int p = 0; p < 4; ++p) { pf[a][p] = 0ULL; pg[a][p] = 0ULL; }

            // h-pass first: batched global loads (MLP 8)
            if (hval) {
                for (int k = 0; k < NCOND; k += 4) {
                    ulonglong2 hA[4], hB[4];
                    #pragma unroll
                    for (int q = 0; q < 4; ++q) {
                        const float* hr = hb + (size_t)(k + q) * NT;
                        hA[q] = *(const ulonglong2*)hr;
                        hB[q] = *(const ulonglong2*)(hr + 4);
                    }
                    #pragma unroll
                    for (int q = 0; q < 4; ++q) {
                        const float* wfp = wd + CF2T + ((k + q) * 32 + c0) * 2;
                        const float* wgp = wd + CG2T + ((k + q) * 32 + c0) * 2;
                        ulonglong2 wfA = *(const ulonglong2*)wfp;
                        ulonglong2 wfB = *(const ulonglong2*)(wfp + 4);
                        ulonglong2 wgA = *(const ulonglong2*)wgp;
                        ulonglong2 wgB = *(const ulonglong2*)(wgp + 4);
                        u64 hv[4] = {hA[q].x, hA[q].y, hB[q].x, hB[q].y};
                        u64 wf_[4] = {wfA.x, wfA.y, wfB.x, wfB.y};
                        u64 wg_[4] = {wgA.x, wgA.y, wgB.x, wgB.y};
                        #pragma unroll
                        for (int cc = 0; cc < 4; ++cc)
                            #pragma unroll
                            for (int p = 0; p < 4; ++p) {
                                pf[cc][p] = fma2(hv[p], wf_[cc], pf[cc][p]);
                                pg[cc][p] = fma2(hv[p], wg_[cc], pg[cc][p]);
                            }
                    }
                }
            }
            // y-pass
            #pragma unroll 2
            for (int k = 0; k < 32; ++k) {
                const float* yr = ybuf + k * TTH + lt0;
                ulonglong2 vA = *(const ulonglong2*)yr;
                ulonglong2 vB = *(const ulonglong2*)(yr + 4);
                const float* wfp = wd + F2T + (k * 32 + c0) * 2;
                const float* wgp = wd + G2T + (k * 32 + c0) * 2;
                ulonglong2 wfA = *(const ulonglong2*)wfp;
                ulonglong2 wfB = *(const ulonglong2*)(wfp + 4);
                ulonglong2 wgA = *(const ulonglong2*)wgp;
                ulonglong2 wgB = *(const ulonglong2*)(wgp + 4);
                u64 yv[4] = {vA.x, vA.y, vB.x, vB.y};
                u64 wf_[4] = {wfA.x, wfA.y, wfB.x, wfB.y};
                u64 wg_[4] = {wgA.x, wgA.y, wgB.x, wgB.y};
                #pragma unroll
                for (int cc = 0; cc < 4; ++cc)
                    #pragma unroll
                    for (int p = 0; p < 4; ++p) {
                        pf[cc][p] = fma2(yv[p], wf_[cc], pf[cc][p]);
                        pg[cc][p] = fma2(yv[p], wg_[cc], pg[cc][p]);
                    }
            }
            #pragma unroll
            for (int cc = 0; cc < 4; ++cc)
                #pragma unroll
                for (int p = 0; p < 4; ++p) {
                    float f0, f1, g0, g1;
                    upk(pf[cc][p], f0, f1); upk(pg[cc][p], g0, g1);
                    zp[cc][p] = pk(fast_tanh(f0) * fast_sigmoid(g0),
                                   fast_tanh(f1) * fast_sigmoid(g1));
                }
        }
        __syncthreads();   // all reads of y done
        #pragma unroll
        for (int cc = 0; cc < 4; ++cc) {
            float* zo = ybuf + (c0 + cc) * TTH + lt0;
            *(ulonglong2*)zo       = make_ulonglong2(zp[cc][0], zp[cc][1]);
            *(ulonglong2*)(zo + 4) = make_ulonglong2(zp[cc][2], zp[cc][3]);
        }
        __syncthreads();   // z complete

        // ---- G3: res += Ow @ z ----
        {
            u64 acc[4][4];
            #pragma unroll
            for (int a = 0; a < 4; ++a)
                #pragma unroll
                for (int p = 0; p < 4; ++p) acc[a][p] = 0ULL;

            #pragma unroll 2
            for (int k = 0; k < 32; ++k) {
                const float* zr = ybuf + k * TTH + lt0;
                ulonglong2 vA = *(const ulonglong2*)zr;
                ulonglong2 vB = *(const ulonglong2*)(zr + 4);
                const float* wp = wd + O2T + (k * 32 + c0) * 2;
                ulonglong2 wA = *(const ulonglong2*)wp;
                ulonglong2 wB = *(const ulonglong2*)(wp + 4);
                u64 zv[4] = {vA.x, vA.y, vB.x, vB.y};
                u64 w_[4] = {wA.x, wA.y, wB.x, wB.y};
                #pragma unroll
                for (int oo = 0; oo < 4; ++oo)
                    #pragma unroll
                    for (int p = 0; p < 4; ++p)
                        acc[oo][p] = fma2(zv[p], w_[oo], acc[oo][p]);
            }
            if (tg0 >= 0) {
                #pragma unroll
                for (int oo = 0; oo < 4; ++oo) {
                    float* rp = res + (c0 + oo) * TTH + lt0;
                    ulonglong2 rA = *(const ulonglong2*)rp;
                    ulonglong2 rB = *(const ulonglong2*)(rp + 4);
                    *(ulonglong2*)rp       = make_ulonglong2(add2(rA.x, acc[oo][0]),
                                                             add2(rA.y, acc[oo][1]));
                    *(ulonglong2*)(rp + 4) = make_ulonglong2(add2(rB.x, acc[oo][2]),
                                                             add2(rB.y, acc[oo][3]));
                }
            }
        }
        __syncthreads();
    }

    // ---- relu(skip) -> ybuf; stage end1 transposed dup into wd ----
    for (int idx = tid; idx < 32 * TTH; idx += NTHREADS) {
        int ch = idx >> 9, lt = idx & (TTH - 1);
        int tg = tgb + lt;
        float xv = (tg >= 0 && tg < NT) ? x[b * NT + tg] : 0.f;
        ybuf[idx] = fmaxf(res[idx] - sw[ch] * xv, 0.f);
    }
    for (int j = tid; j < 8192; j += NTHREADS) {   // end1 [256][32] -> [k][s] dup
        int s = j >> 5, k = j & 31;
        float v = end1_w[j];
        *(float2*)(wd + (k * 256 + s) * 2) = make_float2(v, v);
    }
    __syncthreads();

    // ---- end head: chunks of 64 timesteps; ebuf[256][64] reuses res ----
    float* ebuf = res;
    const int cb2 = tid >> 3;   // 0..63
    const int tb8 = tid & 7;    // 0..7
    const int s0  = cb2 * 4;
    for (int chunk = 0; chunk < 8; ++chunk) {
        int ltc = HALO + chunk * 64 + tb8 * 8;
        bool active = (ltc < TTH);
        if (active) {  // E1: e = relu(end1 @ skip)
            u64 acc[4][4];
            #pragma unroll
            for (int a = 0; a < 4; ++a)
                #pragma unroll
                for (int p = 0; p < 4; ++p) acc[a][p] = 0ULL;
            #pragma unroll 2
            for (int k = 0; k < 32; ++k) {
                const float* yr = ybuf + k * TTH + ltc;
                ulonglong2 vA = *(const ulonglong2*)yr;
                ulonglong2 vB = *(const ulonglong2*)(yr + 4);
                const float* wp = wd + (k * 256 + s0) * 2;
                ulonglong2 wA = *(const ulonglong2*)wp;
                ulonglong2 wB = *(const ulonglong2*)(wp + 4);
                u64 yv[4] = {vA.x, vA.y, vB.x, vB.y};
                u64 w_[4] = {wA.x, wA.y, wB.x, wB.y};
                #pragma unroll
                for (int ss = 0; ss < 4; ++ss)
                    #pragma unroll
                    for (int p = 0; p < 4; ++p)
                        acc[ss][p] = fma2(yv[p], w_[ss], acc[ss][p]);
            }
            #pragma unroll
            for (int ss = 0; ss < 4; ++ss) {
                float* eo = ebuf + (s0 + ss) * 64 + tb8 * 8;
                #pragma unroll
                for (int p = 0; p < 4; ++p) {
                    float a0, a1; upk(acc[ss][p], a0, a1);
                    *(float2*)(eo + 2 * p) = make_float2(fmaxf(a0, 0.f), fmaxf(a1, 0.f));
                }
            }
        }
        __syncthreads();
        if (active) {  // E2: logit = end2 @ e
            u64 acc[4][4];
            #pragma unroll
            for (int a = 0; a < 4; ++a)
                #pragma unroll
                for (int p = 0; p < 4; ++p) acc[a][p] = 0ULL;
            #pragma unroll 4
            for (int k = 0; k < 256; ++k) {
                const float* er = ebuf + k * 64 + tb8 * 8;
                ulonglong2 vA = *(const ulonglong2*)er;
                ulonglong2 vB = *(const ulonglong2*)(er + 4);
                u64 ev[4] = {vA.x, vA.y, vB.x, vB.y};
                #pragma unroll
                for (int cc = 0; cc < 4; ++cc) {
                    float w = __ldg(end2_w + (s0 + cc) * 256 + k);
                    u64 wp2 = pk(w, w);
                    #pragma unroll
                    for (int p = 0; p < 4; ++p)
                        acc[cc][p] = fma2(ev[p], wp2, acc[cc][p]);
                }
            }
            int tgc = tgb + ltc;
            #pragma unroll
            for (int cc = 0; cc < 4; ++cc) {
                float* op = out + ((size_t)(b * 256 + s0 + cc)) * NT + tgc;
                if (tgc + 8 <= NT) {
                    #pragma unroll
                    for (int p = 0; p < 4; ++p)
                        *(u64*)(op + 2 * p) = acc[cc][p];
                } else {
                    #pragma unroll
                    for (int p = 0; p < 4; ++p) {
                        float a0, a1; upk(acc[cc][p], a0, a1);
                        if (tgc + 2 * p     < NT) op[2 * p]     = a0;
                        if (tgc + 2 * p + 1 < NT) op[2 * p + 1] = a1;
                    }
                }
            }
        }
        __syncthreads();
    }
}

extern "C" void kernel_launch(void* const* d_in, const int* in_sizes, int n_in,
                              void* d_out, int out_size) {
    const float* x       = (const float*)d_in[0];
    const float* h       = (const float*)d_in[1];
    const float* start_w = (const float*)d_in[2];
    const float* dil_w   = (const float*)d_in[3];
    const float* f_w     = (const float*)d_in[4];
    const float* g_w     = (const float*)d_in[5];
    const float* cf_w    = (const float*)d_in[6];
    const float* cg_w    = (const float*)d_in[7];
    const float* out_w   = (const float*)d_in[8];
    const float* end1_w  = (const float*)d_in[9];
    const float* end2_w  = (const float*)d_in[10];
    float* out = (float*)d_out;

    cudaFuncSetAttribute(wavenet_kernel,
                         cudaFuncAttributeMaxDynamicSharedMemorySize, SMEM_BYTES);
    wavenet_kernel<<<NB * TILES_PER_B, NTHREADS, SMEM_BYTES>>>(
        x, h, start_w, dil_w, f_w, g_w, cf_w, cg_w, out_w, end1_w, end2_w, out);
}